// round 15
// baseline (speedup 1.0000x reference)
#include <cuda_runtime.h>
#include <cuda_fp16.h>
#include <mma.h>
#include <math.h>
#include <float.h>
#include <stdint.h>

using namespace nvcuda;

constexpr int B  = 8;
constexpr int S  = 1024;
constexpr int H  = 8;
constexpr int DK = 64;
constexpr int D  = 512;
constexpr int BH  = B * H;     // 64
constexpr int BHS = BH * S;    // 65536
constexpr int MR  = B * S;     // 8192

// ---------------- device scratch ----------------
__device__ float g_att[(size_t)BH * S * S];                 // raw scores
__device__ __half g_sch[(size_t)BH * S * S];                // prob (single plane)
__device__ __half g_s2h[(size_t)BH * S * S];                // prob^2 (single plane)
__device__ __half g_Qh[(size_t)BHS * 128];
__device__ __half g_Ql[(size_t)BHS * 128];
__device__ __half g_Kh[(size_t)BHS * 128];
__device__ __half g_Kl[(size_t)BHS * 128];
__device__ __half g_Vm[(size_t)BHS * DK];                   // single-plane V
__device__ __half g_Vc[(size_t)BHS * DK];
__device__ __half g_A6h[(size_t)6 * MR * D];
__device__ __half g_A6l[(size_t)6 * MR * D];
__device__ __half g_W8h[8 * D * D];
__device__ __half g_W8l[8 * D * D];                          // unused (kept for ptr slots)
__device__ __half g_cmh[(size_t)MR * D];
__device__ __half g_cml[(size_t)MR * D];
__device__ __half g_cch[(size_t)MR * D];
__device__ __half g_ccl[(size_t)MR * D];
// raw fp32 covariance projections (pre-sqrt) for exact tq/tk
__device__ float g_rawQc[(size_t)BHS * DK];
__device__ float g_rawKc[(size_t)BHS * DK];
__device__ float g_tq[BHS];
__device__ float g_tk[BHS];

// ---------------- cp.async helpers ----------------
#define CP16(dst, src) asm volatile( \
    "cp.async.cg.shared.global [%0], [%1], 16;" \
    :: "r"((uint32_t)__cvta_generic_to_shared(dst)), "l"(src))
#define CP_COMMIT() asm volatile("cp.async.commit_group;")
#define CP_WAIT(n)  asm volatile("cp.async.wait_group %0;" :: "n"(n))

struct Ptr6f { const float* p[6]; };
struct Ptr8f { const float* p[8]; };

// ---------------- pack 8 fp32 -> fp16 hi/lo uint4 pair --------------------
__device__ __forceinline__ void pack8h(const float* v, uint4& uh, uint4& ul)
{
    __align__(16) unsigned short hh[8];
    __align__(16) unsigned short ll[8];
#pragma unroll
    for (int c = 0; c < 8; c++) {
        const __half x = __float2half_rn(v[c]);
        hh[c] = __half_as_ushort(x);
        ll[c] = __half_as_ushort(__float2half_rn(v[c] - __half2float(x)));
    }
    uh = *(uint4*)hh;
    ul = *(uint4*)ll;
}

// ---------------- batched fp32 -> fp16 hi/lo split (inputs) ----------------
__global__ void u_split6(Ptr6f xs)
{
    const size_t zo = (size_t)blockIdx.z * MR * D;
    const int i = (blockIdx.x * 256 + threadIdx.x) * 4;
    const float4 fv = *(const float4*)(xs.p[blockIdx.z] + i);
    const float v[4] = {fv.x, fv.y, fv.z, fv.w};
    __align__(8) unsigned short hh[4], ll[4];
#pragma unroll
    for (int c = 0; c < 4; c++) {
        const __half x = __float2half_rn(v[c]);
        hh[c] = __half_as_ushort(x);
        ll[c] = __half_as_ushort(__float2half_rn(v[c] - __half2float(x)));
    }
    *(uint2*)(g_A6h + zo + i) = *(uint2*)hh;
    *(uint2*)(g_A6l + zo + i) = *(uint2*)ll;
}

// ---------------- batched W[K,N] -> W^T[N,K] fp16 (hi only; lo unused) -----
__global__ void u_splitWt8(Ptr8f ws)
{
    __shared__ float tile[32][33];
    const size_t zo = (size_t)blockIdx.z * D * D;
    const float* W = ws.p[blockIdx.z];
    const int k0 = blockIdx.y * 32, n0 = blockIdx.x * 32;
    const int tx = threadIdx.x & 31, tw = threadIdx.x >> 5;
    for (int r = tw; r < 32; r += 8)
        tile[r][tx] = W[(size_t)(k0 + r) * D + n0 + tx];
    __syncthreads();
    for (int r = tw; r < 32; r += 8) {
        const float v = tile[tx][r];
        const size_t o = zo + (size_t)(n0 + r) * D + k0 + tx;
        g_W8h[o] = __float2half_rn(v);
    }
}

// ===================  double-buffered WMMA GEMM core  ======================
// MODE 1: aH*bH + aL*bH (2-term, drop B-lo; skips Bl prefetch)
// MODE 2: aH*bH + aH*bL (2-term, drop A-lo; skips Al prefetch)
constexpr int GP = 24;   // smem pitch (16 + 8 pad)

#define GEMM_PREFETCH(dstbuf, koff)                                            \
    _Pragma("unroll")                                                          \
    for (int i = 0; i < 4; i++) {                                              \
        const int c = tid + i * 256;                                           \
        const int mtx = c >> 8, rr = (c & 255) >> 1, col8 = (c & 1) * 8;       \
        const bool skip = (mode == 1 && mtx == 3) || (mode == 2 && mtx == 1);  \
        if (!skip)                                                             \
            CP16(&buf[dstbuf][mtx][rr * GP + col8],                            \
                 srcs[mtx] + (size_t)(baserow[mtx] + rr) * ldv + (koff) + col8); \
    }

#define GEMM_MAINLOOP(Ah, Al, Bh, Bl, LD, NITER, MODE)                         \
    const __half* srcs[4] = {Ah, Al, Bh, Bl};                                  \
    const int baserow[4] = {m0, m0, n0, n0};                                   \
    const int ldv = (LD);                                                      \
    const int mode = (MODE);                                                   \
    wmma::fragment<wmma::accumulator, 16, 16, 16, float> acc[4][2];            \
    _Pragma("unroll")                                                          \
    for (int mi = 0; mi < 4; mi++)                                             \
        _Pragma("unroll")                                                      \
        for (int nj = 0; nj < 2; nj++) wmma::fill_fragment(acc[mi][nj], 0.f);  \
    GEMM_PREFETCH(0, 0)                                                        \
    CP_COMMIT();                                                               \
    for (int kt = 0; kt < (NITER); kt++) {                                     \
        CP_WAIT(0);                                                            \
        __syncthreads();                                                       \
        if (kt + 1 < (NITER)) {                                                \
            const int bn = (kt + 1) & 1;                                       \
            GEMM_PREFETCH(bn, (kt + 1) * 16)                                   \
            CP_COMMIT();                                                       \
        }                                                                      \
        const __half* sAh = buf[kt & 1][0];                                    \
        const __half* sAl = buf[kt & 1][1];                                    \
        const __half* sBh = buf[kt & 1][2];                                    \
        const __half* sBl = buf[kt & 1][3];                                    \
        wmma::fragment<wmma::matrix_a, 16, 16, 16, __half, wmma::row_major> aH[4], aL[4]; \
        _Pragma("unroll")                                                      \
        for (int mi = 0; mi < 4; mi++) {                                       \
            const int row = warp_m * 64 + mi * 16;                             \
            wmma::load_matrix_sync(aH[mi], sAh + row * GP, GP);                \
            if (mode != 2) wmma::load_matrix_sync(aL[mi], sAl + row * GP, GP); \
        }                                                                      \
        _Pragma("unroll")                                                      \
        for (int nj = 0; nj < 2; nj++) {                                       \
            const int col = warp_n * 32 + nj * 16;                             \
            wmma::fragment<wmma::matrix_b, 16, 16, 16, __half, wmma::col_major> bH, bL; \
            wmma::load_matrix_sync(bH, sBh + col * GP, GP);                    \
            if (mode != 1) wmma::load_matrix_sync(bL, sBl + col * GP, GP);     \
            _Pragma("unroll")                                                  \
            for (int mi = 0; mi < 4; mi++) {                                   \
                wmma::mma_sync(acc[mi][nj], aH[mi], bH, acc[mi][nj]);          \
                if (mode != 1) wmma::mma_sync(acc[mi][nj], aH[mi], bL, acc[mi][nj]); \
                if (mode != 2) wmma::mma_sync(acc[mi][nj], aL[mi], bH, acc[mi][nj]); \
            }                                                                  \
        }                                                                      \
    }                                                                          \
    __syncthreads();

// ---------------- projection GEMM (z = 0..5), fused epilogue, all 2-term ----
// z: 0 qm, 1 qc(sqrt), 2 km, 3 kc(sqrt), 4 vm, 5 vc
__global__ void __launch_bounds__(256, 2) u_gemm_proj(Ptr6f biases)
{
    __shared__ __align__(16) __half buf[2][4][128 * GP];  // 48 KB
    const int z = blockIdx.z;
    const __half* Ah = g_A6h + (size_t)z * MR * D;
    const __half* Al = g_A6l + (size_t)z * MR * D;
    const __half* Bh = g_W8h + (size_t)z * D * D;
    const __half* Bl = g_W8l + (size_t)z * D * D;
    const float* bias = biases.p[z];
    const int tid = threadIdx.x, wid = tid >> 5, lane = tid & 31;
    const int m0 = blockIdx.y * 128, n0 = blockIdx.x * 128;
    const int warp_m = wid >> 2, warp_n = wid & 3;

    GEMM_MAINLOOP(Ah, Al, Bh, Bl, D, 32, 1)

    float* epi = (float*)buf + wid * 256;
#pragma unroll
    for (int mi = 0; mi < 4; mi++) {
#pragma unroll
        for (int nj = 0; nj < 2; nj++) {
            wmma::store_matrix_sync(epi, acc[mi][nj], 16, wmma::mem_row_major);
            __syncwarp();
            const int r  = lane >> 1;
            const int c0 = (lane & 1) * 8;
            const int m  = m0 + warp_m * 64 + mi * 16 + r;
            const int n  = n0 + warp_n * 32 + nj * 16 + c0;
            float v[8];
#pragma unroll
            for (int c = 0; c < 8; c++) v[c] = epi[r * 16 + c0 + c] + bias[n + c];
            const int b = m >> 10, s = m & (S - 1);
            const int h = n >> 6, d = n & 63;
            if (z < 4) {
                if (z & 1) {
                    float* raw = (z == 1) ? g_rawQc : g_rawKc;
                    const size_t ro = (((size_t)(b * H + h)) * S + s) * 64 + d;
                    *(float4*)(raw + ro)     = make_float4(v[0], v[1], v[2], v[3]);
                    *(float4*)(raw + ro + 4) = make_float4(v[4], v[5], v[6], v[7]);
#pragma unroll
                    for (int c = 0; c < 8; c++) v[c] = sqrtf(fmaxf(v[c], 1e-24f));
                }
                __half* dh = (z < 2) ? g_Qh : g_Kh;
                __half* dl = (z < 2) ? g_Ql : g_Kl;
                const size_t o = (((size_t)(b * H + h)) * S + s) * 128 + (z & 1) * 64 + d;
                uint4 uh, ul;
                pack8h(v, uh, ul);
                *(uint4*)(dh + o) = uh;
                *(uint4*)(dl + o) = ul;
            } else {
                __half* dv = (z == 4) ? g_Vm : g_Vc;
                __align__(16) unsigned short t[8];
#pragma unroll
                for (int c = 0; c < 8; c++) t[c] = __half_as_ushort(__float2half_rn(v[c]));
                const size_t o = (((size_t)(b * H + h)) * S + s) * 64 + d;
                *(uint4*)(dv + o) = *(uint4*)t;
            }
            __syncwarp();
        }
    }
}

// ---------------- output GEMM (z = 0 mean, 1 cov), 2-term ------------------
__global__ void __launch_bounds__(256, 2) u_gemm_out(const float* bias0, const float* bias1,
                                                     float* out)
{
    __shared__ __align__(16) __half buf[2][4][128 * GP];
    const int z = blockIdx.z;
    const __half* Ah = z ? g_cch : g_cmh;
    const __half* Al = z ? g_ccl : g_cml;
    const __half* Bh = g_W8h + (size_t)(6 + z) * D * D;
    const __half* Bl = g_W8l + (size_t)(6 + z) * D * D;
    const float* bias = z ? bias1 : bias0;
    const int tid = threadIdx.x, wid = tid >> 5, lane = tid & 31;
    const int m0 = blockIdx.y * 128, n0 = blockIdx.x * 128;
    const int warp_m = wid >> 2, warp_n = wid & 3;

    GEMM_MAINLOOP(Ah, Al, Bh, Bl, D, 32, 1)

    float* epi = (float*)buf + wid * 256;
    float* dstm = out + (size_t)z * MR * D;
#pragma unroll
    for (int mi = 0; mi < 4; mi++) {
#pragma unroll
        for (int nj = 0; nj < 2; nj++) {
            wmma::store_matrix_sync(epi, acc[mi][nj], 16, wmma::mem_row_major);
            __syncwarp();
            const int r  = lane >> 1;
            const int c0 = (lane & 1) * 8;
            const int m  = m0 + warp_m * 64 + mi * 16 + r;
            const int n  = n0 + warp_n * 32 + nj * 16 + c0;
            float v[8];
#pragma unroll
            for (int c = 0; c < 8; c++) v[c] = epi[r * 16 + c0 + c] + bias[n + c];
            float* dst = dstm + (size_t)m * D + n;
            *(float4*)(dst)     = make_float4(v[0], v[1], v[2], v[3]);
            *(float4*)(dst + 4) = make_float4(v[4], v[5], v[6], v[7]);
            __syncwarp();
        }
    }
}

// ---------------- exact row stats: tq = sum(qm^2) + sum(raw qc) ------------
__global__ void u_rownorm()
{
    const int row  = blockIdx.x * 8 + (threadIdx.x >> 5);
    const int lane = threadIdx.x & 31;
    const __half* ph = (blockIdx.y ? g_Kh : g_Qh) + (size_t)row * 128;
    const __half* pl = (blockIdx.y ? g_Kl : g_Ql) + (size_t)row * 128;
    const float* pc = (blockIdx.y ? g_rawKc : g_rawQc) + (size_t)row * DK;
    const float a0 = __half2float(ph[lane])      + __half2float(pl[lane]);
    const float a1 = __half2float(ph[lane + 32]) + __half2float(pl[lane + 32]);
    const float c0 = pc[lane], c1 = pc[lane + 32];
    float v = a0 * a0 + a1 * a1 + c0 + c1;
#pragma unroll
    for (int o = 16; o; o >>= 1) v += __shfl_xor_sync(~0u, v, o);
    if (lane == 0) (blockIdx.y ? g_tk : g_tq)[row] = v;
}

// ---------------- WMMA scores: 128x128 causal tiles, 2-term (drop Q-lo) ----
__global__ void __launch_bounds__(256, 2) u_scores_wmma()
{
    __shared__ __align__(16) __half buf[2][4][128 * GP];  // 48 KB
    const int bh = blockIdx.y;
    int tq = (int)((sqrtf(8.f * blockIdx.x + 1.f) - 1.f) * 0.5f);
    while ((tq + 1) * (tq + 2) / 2 <= (int)blockIdx.x) tq++;
    while (tq * (tq + 1) / 2 > (int)blockIdx.x) tq--;
    const int tk = blockIdx.x - tq * (tq + 1) / 2;
    const int qb = tq * 128, kb = tk * 128;

    const int tid = threadIdx.x, wid = tid >> 5, lane = tid & 31;
    const int warp_m = wid >> 2, warp_n = wid & 3;
    const int m0 = 0, n0 = 0;
    const __half* Qh = g_Qh + ((size_t)bh * S + qb) * 128;
    const __half* Ql = g_Ql + ((size_t)bh * S + qb) * 128;
    const __half* Kh = g_Kh + ((size_t)bh * S + kb) * 128;
    const __half* Kl = g_Kl + ((size_t)bh * S + kb) * 128;

    GEMM_MAINLOOP(Qh, Ql, Kh, Kl, 128, 8, 2)

    float* att = g_att + (size_t)bh * S * S;
    const float* tqv = g_tq + bh * S;
    const float* tkv = g_tk + bh * S;

    float* epi = (float*)buf + wid * 256;
#pragma unroll
    for (int mi = 0; mi < 4; mi++) {
#pragma unroll
        for (int nj = 0; nj < 2; nj++) {
            wmma::store_matrix_sync(epi, acc[mi][nj], 16, wmma::mem_row_major);
            __syncwarp();
            const int r  = lane >> 1;
            const int c0 = (lane & 1) * 8;
            const int q  = qb + warp_m * 64 + mi * 16 + r;
            const int k  = kb + warp_n * 32 + nj * 16 + c0;
            const float tq2 = tqv[q];
            float v[8];
#pragma unroll
            for (int c = 0; c < 8; c++)
                v[c] = 0.25f * epi[r * 16 + c0 + c] - 0.125f * (tq2 + tkv[k + c]);
            float* dst = att + (size_t)q * S + k;
            *(float4*)(dst)     = make_float4(v[0], v[1], v[2], v[3]);
            *(float4*)(dst + 4) = make_float4(v[4], v[5], v[6], v[7]);
            __syncwarp();
        }
    }
}

// ---------------- warp-per-row decay: softmax->cumsum->decay->softmax ------
// 8 warps/block, one q-row per warp, lane owns contiguous 32-elem chunk.
// No block barriers; all reductions are warp shuffles.
__global__ void __launch_bounds__(256) u_decay(const float* __restrict__ gammas)
{
    const int w = threadIdx.x >> 5, lane = threadIdx.x & 31;
    const int q  = blockIdx.x * 8 + w;
    const int bh = blockIdx.y;
    const int L  = q + 1;
    const int Lr = (L + 127) & ~127;
    const float* row = g_att + ((size_t)bh * S + q) * S;

    const float g = gammas[bh & (H - 1)];
    const float gamma = -log1pf(expf(g));

    const int base = lane * 32;
    const int nv = min(32, max(0, L - base));   // valid elems in this lane

    float s[32];
#pragma unroll
    for (int i = 0; i < 32; i += 4) {
        if (i + 4 <= nv) {
            const float4 v = *(const float4*)(row + base + i);
            s[i] = v.x; s[i+1] = v.y; s[i+2] = v.z; s[i+3] = v.w;
        } else {
#pragma unroll
            for (int j = 0; j < 4; j++)
                s[i + j] = (i + j < nv) ? row[base + i + j] : 0.f;
        }
    }

    // softmax #1 max
    float m = -FLT_MAX;
#pragma unroll
    for (int i = 0; i < 32; i++) if (i < nv) m = fmaxf(m, s[i]);
#pragma unroll
    for (int o = 16; o; o >>= 1) m = fmaxf(m, __shfl_xor_sync(~0u, m, o));

    // lane-local sum of exp
    float run = 0.f;
#pragma unroll
    for (int i = 0; i < 32; i++) if (i < nv) run += expf(s[i] - m);

    // warp inclusive scan -> lane-exclusive prefix + total
    float x = run;
#pragma unroll
    for (int o = 1; o < 32; o <<= 1) {
        const float y = __shfl_up_sync(~0u, x, o);
        if (lane >= o) x += y;
    }
    const float laneExcl = x - run;
    const float tot = __shfl_sync(~0u, x, 31);
    const float invT = 1.f / tot;

    // decay-modified logits (overwrite s with l), track m2
    float m2 = -FLT_MAX;
    float run2 = laneExcl;
#pragma unroll
    for (int i = 0; i < 32; i++) {
        if (i < nv) {
            run2 += expf(s[i] - m);
            const float cum  = run2 * invT;
            const float tail = fmaxf(1.f - cum, 0.f);
            const float pos  = (float)(q - (base + i));
            const float dist = sqrtf(tail * pos);
            float eff = expf(gamma * dist);
            eff = fminf(fmaxf(eff, 1e-5f), 1e5f);
            s[i] = s[i] * eff;
            m2 = fmaxf(m2, s[i]);
        }
    }
#pragma unroll
    for (int o = 16; o; o >>= 1) m2 = fmaxf(m2, __shfl_xor_sync(~0u, m2, o));

    // softmax #2 (overwrite s with e)
    float es = 0.f;
#pragma unroll
    for (int i = 0; i < 32; i++) {
        if (i < nv) {
            s[i] = expf(s[i] - m2);
            es += s[i];
        }
    }
#pragma unroll
    for (int o = 16; o; o >>= 1) es += __shfl_xor_sync(~0u, es, o);
    const float invE = 1.f / es;

    // write prob + prob^2 planes (zero-fill up to Lr)
    if (base < Lr) {
        const size_t pidx = ((size_t)bh * S + q) * S + base;
#pragma unroll
        for (int i = 0; i < 32; i += 8) {
            __align__(16) unsigned short t1[8], t2[8];
#pragma unroll
            for (int j = 0; j < 8; j++) {
                const float pv = (q == 0 || i + j >= nv) ? 0.f : s[i + j] * invE;
                t1[j] = __half_as_ushort(__float2half_rn(pv));
                t2[j] = __half_as_ushort(__float2half_rn(pv * pv));
            }
            *(uint4*)(g_sch + pidx + i) = *(uint4*)t1;
            *(uint4*)(g_s2h + pidx + i) = *(uint4*)t2;
        }
    }
}

// ---------------- WMMA AV (1-term): mean = p@Vm, cov = p2@Vc ---------------
constexpr int AP  = 24;
constexpr int BPp = 72;

__global__ void __launch_bounds__(256, 2) u_av_wmma()
{
    __shared__ __align__(16) __half sA[2][2][128 * AP];
    __shared__ __align__(16) __half sB[2][2][16 * BPp];

    const int bh = blockIdx.y;
    const int qb = (7 - blockIdx.x) * 128;
    const int tid = threadIdx.x, wid = tid >> 5, lane = tid & 31;
    const int wg = wid >> 2, w4 = wid & 3;

    const size_t aoff = ((size_t)bh * S + qb) * S;
    const size_t vb   = (size_t)bh * S * DK;
    const __half* Ap[2] = {g_sch + aoff, g_s2h + aoff};
    const __half* Vp[2] = {g_Vm + vb, g_Vc + vb};

    wmma::fragment<wmma::accumulator, 16, 16, 16, float> acc[2][4];
#pragma unroll
    for (int mi = 0; mi < 2; mi++)
#pragma unroll
        for (int nj = 0; nj < 4; nj++) wmma::fill_fragment(acc[mi][nj], 0.f);

    const int NITER = (qb + 128) / 16;

#define AV_PREFETCH(bufi, kb)                                                  \
    _Pragma("unroll")                                                          \
    for (int i = 0; i < 2; i++) {                                              \
        const int c = tid + i * 256;                                           \
        const int pl = c >> 8, idx = c & 255;                                  \
        const int rr = idx >> 1, col8 = (idx & 1) * 8;                         \
        CP16(&sA[bufi][pl][rr * AP + col8], Ap[pl] + (size_t)rr * S + (kb) + col8); \
    }                                                                          \
    {                                                                          \
        const int mtx = tid >> 7, idx = tid & 127;                             \
        const int rr = idx >> 3, col8 = (idx & 7) * 8;                         \
        CP16(&sB[bufi][mtx][rr * BPp + col8], Vp[mtx] + (size_t)((kb) + rr) * DK + col8); \
    }

    AV_PREFETCH(0, 0)
    CP_COMMIT();

    for (int kt = 0; kt < NITER; kt++) {
        CP_WAIT(0);
        __syncthreads();
        if (kt + 1 < NITER) {
            const int bn = (kt + 1) & 1;
            AV_PREFETCH(bn, (kt + 1) * 16)
            CP_COMMIT();
        }
        const int cur = kt & 1;
        const __half* aPp = sA[cur][wg];
        const __half* bVp = sB[cur][wg];

        wmma::fragment<wmma::matrix_a, 16, 16, 16, __half, wmma::row_major> aP[2];
#pragma unroll
        for (int mi = 0; mi < 2; mi++) {
            const int row = w4 * 32 + mi * 16;
            wmma::load_matrix_sync(aP[mi], aPp + row * AP, AP);
        }
#pragma unroll
        for (int nj = 0; nj < 4; nj++) {
            wmma::fragment<wmma::matrix_b, 16, 16, 16, __half, wmma::row_major> bV;
            wmma::load_matrix_sync(bV, bVp + nj * 16, BPp);
#pragma unroll
            for (int mi = 0; mi < 2; mi++)
                wmma::mma_sync(acc[mi][nj], aP[mi], bV, acc[mi][nj]);
        }
    }
    __syncthreads();

    const int b = bh >> 3, h = bh & 7;
    __half* dh = wg ? g_cch : g_cmh;
    __half* dl = wg ? g_ccl : g_cml;
    float* epi = (float*)sA + wid * 256;
#pragma unroll
    for (int mi = 0; mi < 2; mi++) {
#pragma unroll
        for (int nj = 0; nj < 4; nj++) {
            wmma::store_matrix_sync(epi, acc[mi][nj], 16, wmma::mem_row_major);
            __syncwarp();
            const int r  = lane >> 1;
            const int c0 = (lane & 1) * 8;
            const int s  = qb + w4 * 32 + mi * 16 + r;
            const int d  = nj * 16 + c0;
            float v[8];
#pragma unroll
            for (int c = 0; c < 8; c++) v[c] = epi[r * 16 + c0 + c];
            uint4 uh, ul;
            pack8h(v, uh, ul);
            const size_t o = ((size_t)(b * S + s)) * D + h * DK + d;
            *(uint4*)(dh + o) = uh;
            *(uint4*)(dl + o) = ul;
            __syncwarp();
        }
    }
#undef AV_PREFETCH
}

// ---------------- host launcher --------------------------------------------
extern "C" void kernel_launch(void* const* d_in, const int* in_sizes, int n_in,
                              void* d_out, int out_size)
{
    const float* q_mean = (const float*)d_in[0];
    const float* q_cov  = (const float*)d_in[1];
    const float* k_mean = (const float*)d_in[2];
    const float* k_cov  = (const float*)d_in[3];
    const float* v_mean = (const float*)d_in[4];
    const float* v_cov  = (const float*)d_in[5];
    const float* Wqm = (const float*)d_in[6];  const float* bqm = (const float*)d_in[7];
    const float* Wqc = (const float*)d_in[8];  const float* bqc = (const float*)d_in[9];
    const float* Wkm = (const float*)d_in[10]; const float* bkm = (const float*)d_in[11];
    const float* Wkc = (const float*)d_in[12]; const float* bkc = (const float*)d_in[13];
    const float* Wvm = (const float*)d_in[14]; const float* bvm = (const float*)d_in[15];
    const float* Wvc = (const float*)d_in[16]; const float* bvc = (const float*)d_in[17];
    const float* Wom = (const float*)d_in[18]; const float* bom = (const float*)d_in[19];
    const float* Woc = (const float*)d_in[20]; const float* boc = (const float*)d_in[21];
    const float* gammas = (const float*)d_in[22];

    float* out = (float*)d_out;

    Ptr6f xs;   xs.p[0] = q_mean; xs.p[1] = q_cov; xs.p[2] = k_mean;
                xs.p[3] = k_cov;  xs.p[4] = v_mean; xs.p[5] = v_cov;
    Ptr8f ws;   ws.p[0] = Wqm; ws.p[1] = Wqc; ws.p[2] = Wkm; ws.p[3] = Wkc;
                ws.p[4] = Wvm; ws.p[5] = Wvc; ws.p[6] = Wom; ws.p[7] = Woc;
    Ptr6f bs;   bs.p[0] = bqm; bs.p[1] = bqc; bs.p[2] = bkm;
                bs.p[3] = bkc; bs.p[4] = bvm; bs.p[5] = bvc;

    u_split6  <<<dim3(MR * D / 1024, 1, 6), 256>>>(xs);
    u_splitWt8<<<dim3(D / 32, D / 32, 8), 256>>>(ws);
    u_gemm_proj<<<dim3(D / 128, MR / 128, 6), 256>>>(bs);
    u_rownorm <<<dim3(BHS / 8, 2), 256>>>();
    u_scores_wmma<<<dim3(36, BH), 256>>>();
    u_decay   <<<dim3(S / 8, BH), 256>>>(gammas);
    u_av_wmma <<<dim3(S / 128, BH), 256>>>();
    u_gemm_out<<<dim3(D / 128, MR / 128, 2), 256>>>(bom, boc, out);
}

// round 16
// speedup vs baseline: 1.0295x; 1.0295x over previous
#include <cuda_runtime.h>
#include <cuda_fp16.h>
#include <mma.h>
#include <math.h>
#include <float.h>
#include <stdint.h>

using namespace nvcuda;

constexpr int B  = 8;
constexpr int S  = 1024;
constexpr int H  = 8;
constexpr int DK = 64;
constexpr int D  = 512;
constexpr int BH  = B * H;     // 64
constexpr int BHS = BH * S;    // 65536
constexpr int MR  = B * S;     // 8192

// ---------------- device scratch ----------------
__device__ float g_att[(size_t)BH * S * S];                 // raw scores
__device__ __half g_sch[(size_t)BH * S * S];                // prob (single plane)
__device__ __half g_Qh[(size_t)BHS * 128];
__device__ __half g_Ql[(size_t)BHS * 128];
__device__ __half g_Kh[(size_t)BHS * 128];
__device__ __half g_Kl[(size_t)BHS * 128];
__device__ __half g_Vm[(size_t)BHS * DK];                   // single-plane V
__device__ __half g_Vc[(size_t)BHS * DK];
__device__ __half g_A6h[(size_t)6 * MR * D];
__device__ __half g_A6l[(size_t)6 * MR * D];
__device__ __half g_W8h[8 * D * D];
__device__ __half g_W8l[8 * D * D];                          // unused (ptr slots)
__device__ __half g_cmh[(size_t)MR * D];
__device__ __half g_cml[(size_t)MR * D];
__device__ __half g_cch[(size_t)MR * D];
__device__ __half g_ccl[(size_t)MR * D];
// raw fp32 covariance projections (pre-sqrt) for exact tq/tk
__device__ float g_rawQc[(size_t)BHS * DK];
__device__ float g_rawKc[(size_t)BHS * DK];
__device__ float g_tq[BHS];
__device__ float g_tk[BHS];

// ---------------- cp.async helpers ----------------
#define CP16(dst, src) asm volatile( \
    "cp.async.cg.shared.global [%0], [%1], 16;" \
    :: "r"((uint32_t)__cvta_generic_to_shared(dst)), "l"(src))
#define CP_COMMIT() asm volatile("cp.async.commit_group;")
#define CP_WAIT(n)  asm volatile("cp.async.wait_group %0;" :: "n"(n))

struct Ptr6f { const float* p[6]; };
struct Ptr8f { const float* p[8]; };

// ---------------- pack 8 fp32 -> fp16 hi/lo uint4 pair --------------------
__device__ __forceinline__ void pack8h(const float* v, uint4& uh, uint4& ul)
{
    __align__(16) unsigned short hh[8];
    __align__(16) unsigned short ll[8];
#pragma unroll
    for (int c = 0; c < 8; c++) {
        const __half x = __float2half_rn(v[c]);
        hh[c] = __half_as_ushort(x);
        ll[c] = __half_as_ushort(__float2half_rn(v[c] - __half2float(x)));
    }
    uh = *(uint4*)hh;
    ul = *(uint4*)ll;
}

// ---------------- batched fp32 -> fp16 hi/lo split (inputs) ----------------
__global__ void u_split6(Ptr6f xs)
{
    const size_t zo = (size_t)blockIdx.z * MR * D;
    const int i = (blockIdx.x * 256 + threadIdx.x) * 4;
    const float4 fv = *(const float4*)(xs.p[blockIdx.z] + i);
    const float v[4] = {fv.x, fv.y, fv.z, fv.w};
    __align__(8) unsigned short hh[4], ll[4];
#pragma unroll
    for (int c = 0; c < 4; c++) {
        const __half x = __float2half_rn(v[c]);
        hh[c] = __half_as_ushort(x);
        ll[c] = __half_as_ushort(__float2half_rn(v[c] - __half2float(x)));
    }
    *(uint2*)(g_A6h + zo + i) = *(uint2*)hh;
    *(uint2*)(g_A6l + zo + i) = *(uint2*)ll;
}

// ---------------- batched W[K,N] -> W^T[N,K] fp16 (hi only) ----------------
__global__ void u_splitWt8(Ptr8f ws)
{
    __shared__ float tile[32][33];
    const size_t zo = (size_t)blockIdx.z * D * D;
    const float* W = ws.p[blockIdx.z];
    const int k0 = blockIdx.y * 32, n0 = blockIdx.x * 32;
    const int tx = threadIdx.x & 31, tw = threadIdx.x >> 5;
    for (int r = tw; r < 32; r += 8)
        tile[r][tx] = W[(size_t)(k0 + r) * D + n0 + tx];
    __syncthreads();
    for (int r = tw; r < 32; r += 8) {
        const float v = tile[tx][r];
        const size_t o = zo + (size_t)(n0 + r) * D + k0 + tx;
        g_W8h[o] = __float2half_rn(v);
    }
}

// ===================  double-buffered WMMA GEMM core  ======================
// MODE 1: aH*bH + aL*bH (2-term, drop B-lo; skips Bl prefetch)
// MODE 2: aH*bH + aH*bL (2-term, drop A-lo; skips Al prefetch)
constexpr int GP = 24;   // smem pitch (16 + 8 pad)

#define GEMM_PREFETCH(dstbuf, koff)                                            \
    _Pragma("unroll")                                                          \
    for (int i = 0; i < 4; i++) {                                              \
        const int c = tid + i * 256;                                           \
        const int mtx = c >> 8, rr = (c & 255) >> 1, col8 = (c & 1) * 8;       \
        const bool skip = (mode == 1 && mtx == 3) || (mode == 2 && mtx == 1);  \
        if (!skip)                                                             \
            CP16(&buf[dstbuf][mtx][rr * GP + col8],                            \
                 srcs[mtx] + (size_t)(baserow[mtx] + rr) * ldv + (koff) + col8); \
    }

#define GEMM_MAINLOOP(Ah, Al, Bh, Bl, LD, NITER, MODE)                         \
    const __half* srcs[4] = {Ah, Al, Bh, Bl};                                  \
    const int baserow[4] = {m0, m0, n0, n0};                                   \
    const int ldv = (LD);                                                      \
    const int mode = (MODE);                                                   \
    wmma::fragment<wmma::accumulator, 16, 16, 16, float> acc[4][2];            \
    _Pragma("unroll")                                                          \
    for (int mi = 0; mi < 4; mi++)                                             \
        _Pragma("unroll")                                                      \
        for (int nj = 0; nj < 2; nj++) wmma::fill_fragment(acc[mi][nj], 0.f);  \
    GEMM_PREFETCH(0, 0)                                                        \
    CP_COMMIT();                                                               \
    for (int kt = 0; kt < (NITER); kt++) {                                     \
        CP_WAIT(0);                                                            \
        __syncthreads();                                                       \
        if (kt + 1 < (NITER)) {                                                \
            const int bn = (kt + 1) & 1;                                       \
            GEMM_PREFETCH(bn, (kt + 1) * 16)                                   \
            CP_COMMIT();                                                       \
        }                                                                      \
        const __half* sAh = buf[kt & 1][0];                                    \
        const __half* sAl = buf[kt & 1][1];                                    \
        const __half* sBh = buf[kt & 1][2];                                    \
        const __half* sBl = buf[kt & 1][3];                                    \
        wmma::fragment<wmma::matrix_a, 16, 16, 16, __half, wmma::row_major> aH[4], aL[4]; \
        _Pragma("unroll")                                                      \
        for (int mi = 0; mi < 4; mi++) {                                       \
            const int row = warp_m * 64 + mi * 16;                             \
            wmma::load_matrix_sync(aH[mi], sAh + row * GP, GP);                \
            if (mode != 2) wmma::load_matrix_sync(aL[mi], sAl + row * GP, GP); \
        }                                                                      \
        _Pragma("unroll")                                                      \
        for (int nj = 0; nj < 2; nj++) {                                       \
            const int col = warp_n * 32 + nj * 16;                             \
            wmma::fragment<wmma::matrix_b, 16, 16, 16, __half, wmma::col_major> bH, bL; \
            wmma::load_matrix_sync(bH, sBh + col * GP, GP);                    \
            if (mode != 1) wmma::load_matrix_sync(bL, sBl + col * GP, GP);     \
            _Pragma("unroll")                                                  \
            for (int mi = 0; mi < 4; mi++) {                                   \
                wmma::mma_sync(acc[mi][nj], aH[mi], bH, acc[mi][nj]);          \
                if (mode != 1) wmma::mma_sync(acc[mi][nj], aH[mi], bL, acc[mi][nj]); \
                if (mode != 2) wmma::mma_sync(acc[mi][nj], aL[mi], bH, acc[mi][nj]); \
            }                                                                  \
        }                                                                      \
    }                                                                          \
    __syncthreads();

// ---------------- projection GEMM (z = 0..5), fused epilogue, all 2-term ----
__global__ void __launch_bounds__(256, 2) u_gemm_proj(Ptr6f biases)
{
    __shared__ __align__(16) __half buf[2][4][128 * GP];  // 48 KB
    const int z = blockIdx.z;
    const __half* Ah = g_A6h + (size_t)z * MR * D;
    const __half* Al = g_A6l + (size_t)z * MR * D;
    const __half* Bh = g_W8h + (size_t)z * D * D;
    const __half* Bl = g_W8l + (size_t)z * D * D;
    const float* bias = biases.p[z];
    const int tid = threadIdx.x, wid = tid >> 5, lane = tid & 31;
    const int m0 = blockIdx.y * 128, n0 = blockIdx.x * 128;
    const int warp_m = wid >> 2, warp_n = wid & 3;

    GEMM_MAINLOOP(Ah, Al, Bh, Bl, D, 32, 1)

    float* epi = (float*)buf + wid * 256;
#pragma unroll
    for (int mi = 0; mi < 4; mi++) {
#pragma unroll
        for (int nj = 0; nj < 2; nj++) {
            wmma::store_matrix_sync(epi, acc[mi][nj], 16, wmma::mem_row_major);
            __syncwarp();
            const int r  = lane >> 1;
            const int c0 = (lane & 1) * 8;
            const int m  = m0 + warp_m * 64 + mi * 16 + r;
            const int n  = n0 + warp_n * 32 + nj * 16 + c0;
            float v[8];
#pragma unroll
            for (int c = 0; c < 8; c++) v[c] = epi[r * 16 + c0 + c] + bias[n + c];
            const int b = m >> 10, s = m & (S - 1);
            const int h = n >> 6, d = n & 63;
            if (z < 4) {
                if (z & 1) {
                    float* raw = (z == 1) ? g_rawQc : g_rawKc;
                    const size_t ro = (((size_t)(b * H + h)) * S + s) * 64 + d;
                    *(float4*)(raw + ro)     = make_float4(v[0], v[1], v[2], v[3]);
                    *(float4*)(raw + ro + 4) = make_float4(v[4], v[5], v[6], v[7]);
#pragma unroll
                    for (int c = 0; c < 8; c++) v[c] = sqrtf(fmaxf(v[c], 1e-24f));
                }
                __half* dh = (z < 2) ? g_Qh : g_Kh;
                __half* dl = (z < 2) ? g_Ql : g_Kl;
                const size_t o = (((size_t)(b * H + h)) * S + s) * 128 + (z & 1) * 64 + d;
                uint4 uh, ul;
                pack8h(v, uh, ul);
                *(uint4*)(dh + o) = uh;
                *(uint4*)(dl + o) = ul;
            } else {
                __half* dv = (z == 4) ? g_Vm : g_Vc;
                __align__(16) unsigned short t[8];
#pragma unroll
                for (int c = 0; c < 8; c++) t[c] = __half_as_ushort(__float2half_rn(v[c]));
                const size_t o = (((size_t)(b * H + h)) * S + s) * 64 + d;
                *(uint4*)(dv + o) = *(uint4*)t;
            }
            __syncwarp();
        }
    }
}

// ---------------- output GEMM (z = 0 mean, 1 cov), 2-term ------------------
__global__ void __launch_bounds__(256, 2) u_gemm_out(const float* bias0, const float* bias1,
                                                     float* out)
{
    __shared__ __align__(16) __half buf[2][4][128 * GP];
    const int z = blockIdx.z;
    const __half* Ah = z ? g_cch : g_cmh;
    const __half* Al = z ? g_ccl : g_cml;
    const __half* Bh = g_W8h + (size_t)(6 + z) * D * D;
    const __half* Bl = g_W8l + (size_t)(6 + z) * D * D;
    const float* bias = z ? bias1 : bias0;
    const int tid = threadIdx.x, wid = tid >> 5, lane = tid & 31;
    const int m0 = blockIdx.y * 128, n0 = blockIdx.x * 128;
    const int warp_m = wid >> 2, warp_n = wid & 3;

    GEMM_MAINLOOP(Ah, Al, Bh, Bl, D, 32, 1)

    float* epi = (float*)buf + wid * 256;
    float* dstm = out + (size_t)z * MR * D;
#pragma unroll
    for (int mi = 0; mi < 4; mi++) {
#pragma unroll
        for (int nj = 0; nj < 2; nj++) {
            wmma::store_matrix_sync(epi, acc[mi][nj], 16, wmma::mem_row_major);
            __syncwarp();
            const int r  = lane >> 1;
            const int c0 = (lane & 1) * 8;
            const int m  = m0 + warp_m * 64 + mi * 16 + r;
            const int n  = n0 + warp_n * 32 + nj * 16 + c0;
            float v[8];
#pragma unroll
            for (int c = 0; c < 8; c++) v[c] = epi[r * 16 + c0 + c] + bias[n + c];
            float* dst = dstm + (size_t)m * D + n;
            *(float4*)(dst)     = make_float4(v[0], v[1], v[2], v[3]);
            *(float4*)(dst + 4) = make_float4(v[4], v[5], v[6], v[7]);
            __syncwarp();
        }
    }
}

// ---------------- exact row stats: tq = sum(qm^2) + sum(raw qc) ------------
__global__ void u_rownorm()
{
    const int row  = blockIdx.x * 8 + (threadIdx.x >> 5);
    const int lane = threadIdx.x & 31;
    const __half* ph = (blockIdx.y ? g_Kh : g_Qh) + (size_t)row * 128;
    const __half* pl = (blockIdx.y ? g_Kl : g_Ql) + (size_t)row * 128;
    const float* pc = (blockIdx.y ? g_rawKc : g_rawQc) + (size_t)row * DK;
    const float a0 = __half2float(ph[lane])      + __half2float(pl[lane]);
    const float a1 = __half2float(ph[lane + 32]) + __half2float(pl[lane + 32]);
    const float c0 = pc[lane], c1 = pc[lane + 32];
    float v = a0 * a0 + a1 * a1 + c0 + c1;
#pragma unroll
    for (int o = 16; o; o >>= 1) v += __shfl_xor_sync(~0u, v, o);
    if (lane == 0) (blockIdx.y ? g_tk : g_tq)[row] = v;
}

// ---------------- WMMA scores: 128x128 causal tiles, 2-term (drop Q-lo) ----
__global__ void __launch_bounds__(256, 2) u_scores_wmma()
{
    __shared__ __align__(16) __half buf[2][4][128 * GP];  // 48 KB
    const int bh = blockIdx.y;
    int tq = (int)((sqrtf(8.f * blockIdx.x + 1.f) - 1.f) * 0.5f);
    while ((tq + 1) * (tq + 2) / 2 <= (int)blockIdx.x) tq++;
    while (tq * (tq + 1) / 2 > (int)blockIdx.x) tq--;
    const int tk = blockIdx.x - tq * (tq + 1) / 2;
    const int qb = tq * 128, kb = tk * 128;

    const int tid = threadIdx.x, wid = tid >> 5, lane = tid & 31;
    const int warp_m = wid >> 2, warp_n = wid & 3;
    const int m0 = 0, n0 = 0;
    const __half* Qh = g_Qh + ((size_t)bh * S + qb) * 128;
    const __half* Ql = g_Ql + ((size_t)bh * S + qb) * 128;
    const __half* Kh = g_Kh + ((size_t)bh * S + kb) * 128;
    const __half* Kl = g_Kl + ((size_t)bh * S + kb) * 128;

    GEMM_MAINLOOP(Qh, Ql, Kh, Kl, 128, 8, 2)

    float* att = g_att + (size_t)bh * S * S;
    const float* tqv = g_tq + bh * S;
    const float* tkv = g_tk + bh * S;

    float* epi = (float*)buf + wid * 256;
#pragma unroll
    for (int mi = 0; mi < 4; mi++) {
#pragma unroll
        for (int nj = 0; nj < 2; nj++) {
            wmma::store_matrix_sync(epi, acc[mi][nj], 16, wmma::mem_row_major);
            __syncwarp();
            const int r  = lane >> 1;
            const int c0 = (lane & 1) * 8;
            const int q  = qb + warp_m * 64 + mi * 16 + r;
            const int k  = kb + warp_n * 32 + nj * 16 + c0;
            const float tq2 = tqv[q];
            float v[8];
#pragma unroll
            for (int c = 0; c < 8; c++)
                v[c] = 0.25f * epi[r * 16 + c0 + c] - 0.125f * (tq2 + tkv[k + c]);
            float* dst = att + (size_t)q * S + k;
            *(float4*)(dst)     = make_float4(v[0], v[1], v[2], v[3]);
            *(float4*)(dst + 4) = make_float4(v[4], v[5], v[6], v[7]);
            __syncwarp();
        }
    }
}

// ---------------- warp-per-row decay: softmax->cumsum->decay->softmax ------
// Writes only the p plane; AV squares on the fly.
__global__ void __launch_bounds__(256) u_decay(const float* __restrict__ gammas)
{
    const int w = threadIdx.x >> 5, lane = threadIdx.x & 31;
    const int q  = blockIdx.x * 8 + w;
    const int bh = blockIdx.y;
    const int L  = q + 1;
    const int Lr = (L + 127) & ~127;
    const float* row = g_att + ((size_t)bh * S + q) * S;

    const float g = gammas[bh & (H - 1)];
    const float gamma = -log1pf(expf(g));

    const int base = lane * 32;
    const int nv = min(32, max(0, L - base));

    float s[32];
#pragma unroll
    for (int i = 0; i < 32; i += 4) {
        if (i + 4 <= nv) {
            const float4 v = *(const float4*)(row + base + i);
            s[i] = v.x; s[i+1] = v.y; s[i+2] = v.z; s[i+3] = v.w;
        } else {
#pragma unroll
            for (int j = 0; j < 4; j++)
                s[i + j] = (i + j < nv) ? row[base + i + j] : 0.f;
        }
    }

    float m = -FLT_MAX;
#pragma unroll
    for (int i = 0; i < 32; i++) if (i < nv) m = fmaxf(m, s[i]);
#pragma unroll
    for (int o = 16; o; o >>= 1) m = fmaxf(m, __shfl_xor_sync(~0u, m, o));

    float run = 0.f;
#pragma unroll
    for (int i = 0; i < 32; i++) if (i < nv) run += expf(s[i] - m);

    float x = run;
#pragma unroll
    for (int o = 1; o < 32; o <<= 1) {
        const float y = __shfl_up_sync(~0u, x, o);
        if (lane >= o) x += y;
    }
    const float laneExcl = x - run;
    const float tot = __shfl_sync(~0u, x, 31);
    const float invT = 1.f / tot;

    float m2 = -FLT_MAX;
    float run2 = laneExcl;
#pragma unroll
    for (int i = 0; i < 32; i++) {
        if (i < nv) {
            run2 += expf(s[i] - m);
            const float cum  = run2 * invT;
            const float tail = fmaxf(1.f - cum, 0.f);
            const float pos  = (float)(q - (base + i));
            const float dist = sqrtf(tail * pos);
            float eff = expf(gamma * dist);
            eff = fminf(fmaxf(eff, 1e-5f), 1e5f);
            s[i] = s[i] * eff;
            m2 = fmaxf(m2, s[i]);
        }
    }
#pragma unroll
    for (int o = 16; o; o >>= 1) m2 = fmaxf(m2, __shfl_xor_sync(~0u, m2, o));

    float es = 0.f;
#pragma unroll
    for (int i = 0; i < 32; i++) {
        if (i < nv) {
            s[i] = expf(s[i] - m2);
            es += s[i];
        }
    }
#pragma unroll
    for (int o = 16; o; o >>= 1) es += __shfl_xor_sync(~0u, es, o);
    const float invE = 1.f / es;

    if (base < Lr) {
        const size_t pidx = ((size_t)bh * S + q) * S + base;
#pragma unroll
        for (int i = 0; i < 32; i += 8) {
            __align__(16) unsigned short t1[8];
#pragma unroll
            for (int j = 0; j < 8; j++) {
                const float pv = (q == 0 || i + j >= nv) ? 0.f : s[i + j] * invE;
                t1[j] = __half_as_ushort(__float2half_rn(pv));
            }
            *(uint4*)(g_sch + pidx + i) = *(uint4*)t1;
        }
    }
}

// ---------------- WMMA AV (1-term): mean = p@Vm, cov = p^2@Vc --------------
// p^2 computed in smem by cov warps (each warp squares only its own rows).
constexpr int AP  = 24;
constexpr int BPp = 72;

__global__ void __launch_bounds__(256, 2) u_av_wmma()
{
    __shared__ __align__(16) __half sA[2][2][128 * AP];   // [stage][{p, p^2}]
    __shared__ __align__(16) __half sB[2][2][16 * BPp];

    const int bh = blockIdx.y;
    const int qb = (7 - blockIdx.x) * 128;
    const int tid = threadIdx.x, wid = tid >> 5, lane = tid & 31;
    const int wg = wid >> 2, w4 = wid & 3;

    const size_t aoff = ((size_t)bh * S + qb) * S;
    const size_t vb   = (size_t)bh * S * DK;
    const __half* Ap0 = g_sch + aoff;
    const __half* Vp[2] = {g_Vm + vb, g_Vc + vb};

    wmma::fragment<wmma::accumulator, 16, 16, 16, float> acc[2][4];
#pragma unroll
    for (int mi = 0; mi < 2; mi++)
#pragma unroll
        for (int nj = 0; nj < 4; nj++) wmma::fill_fragment(acc[mi][nj], 0.f);

    const int NITER = (qb + 128) / 16;

#define AV_PREFETCH(bufi, kb)                                                  \
    {                                                                          \
        const int rr = tid >> 1, col8 = (tid & 1) * 8;                         \
        CP16(&sA[bufi][0][rr * AP + col8], Ap0 + (size_t)rr * S + (kb) + col8);\
        const int mtx = tid >> 7, idx = tid & 127;                             \
        const int rr2 = idx >> 3, c8 = (idx & 7) * 8;                          \
        CP16(&sB[bufi][mtx][rr2 * BPp + c8], Vp[mtx] + (size_t)((kb) + rr2) * DK + c8); \
    }

    AV_PREFETCH(0, 0)
    CP_COMMIT();

    for (int kt = 0; kt < NITER; kt++) {
        CP_WAIT(0);
        __syncthreads();
        if (kt + 1 < NITER) {
            const int bn = (kt + 1) & 1;
            AV_PREFETCH(bn, (kt + 1) * 16)
            CP_COMMIT();
        }
        const int cur = kt & 1;

        if (wg == 1) {
            // square own rows [w4*32, w4*32+32): 1 row/lane, 8 half2 each
            const __half* src = sA[cur][0];
            __half* dst = sA[cur][1];
            const int r = w4 * 32 + lane;
#pragma unroll
            for (int c = 0; c < 16; c += 2) {
                const __half2 v = *(const __half2*)(src + r * AP + c);
                *(__half2*)(dst + r * AP + c) = __hmul2(v, v);
            }
            __syncwarp();
        }

        const __half* aPp = sA[cur][wg];
        const __half* bVp = sB[cur][wg];

        wmma::fragment<wmma::matrix_a, 16, 16, 16, __half, wmma::row_major> aP[2];
#pragma unroll
        for (int mi = 0; mi < 2; mi++) {
            const int row = w4 * 32 + mi * 16;
            wmma::load_matrix_sync(aP[mi], aPp + row * AP, AP);
        }
#pragma unroll
        for (int nj = 0; nj < 4; nj++) {
            wmma::fragment<wmma::matrix_b, 16, 16, 16, __half, wmma::row_major> bV;
            wmma::load_matrix_sync(bV, bVp + nj * 16, BPp);
#pragma unroll
            for (int mi = 0; mi < 2; mi++)
                wmma::mma_sync(acc[mi][nj], aP[mi], bV, acc[mi][nj]);
        }
    }
    __syncthreads();

    const int b = bh >> 3, h = bh & 7;
    __half* dh = wg ? g_cch : g_cmh;
    __half* dl = wg ? g_ccl : g_cml;
    float* epi = (float*)sA + wid * 256;
#pragma unroll
    for (int mi = 0; mi < 2; mi++) {
#pragma unroll
        for (int nj = 0; nj < 4; nj++) {
            wmma::store_matrix_sync(epi, acc[mi][nj], 16, wmma::mem_row_major);
            __syncwarp();
            const int r  = lane >> 1;
            const int c0 = (lane & 1) * 8;
            const int s  = qb + w4 * 32 + mi * 16 + r;
            const int d  = nj * 16 + c0;
            float v[8];
#pragma unroll
            for (int c = 0; c < 8; c++) v[c] = epi[r * 16 + c0 + c];
            uint4 uh, ul;
            pack8h(v, uh, ul);
            const size_t o = ((size_t)(b * S + s)) * D + h * DK + d;
            *(uint4*)(dh + o) = uh;
            *(uint4*)(dl + o) = ul;
            __syncwarp();
        }
    }
#undef AV_PREFETCH
}

// ---------------- host launcher --------------------------------------------
extern "C" void kernel_launch(void* const* d_in, const int* in_sizes, int n_in,
                              void* d_out, int out_size)
{
    const float* q_mean = (const float*)d_in[0];
    const float* q_cov  = (const float*)d_in[1];
    const float* k_mean = (const float*)d_in[2];
    const float* k_cov  = (const float*)d_in[3];
    const float* v_mean = (const float*)d_in[4];
    const float* v_cov  = (const float*)d_in[5];
    const float* Wqm = (const float*)d_in[6];  const float* bqm = (const float*)d_in[7];
    const float* Wqc = (const float*)d_in[8];  const float* bqc = (const float*)d_in[9];
    const float* Wkm = (const float*)d_in[10]; const float* bkm = (const float*)d_in[11];
    const float* Wkc = (const float*)d_in[12]; const float* bkc = (const float*)d_in[13];
    const float* Wvm = (const float*)d_in[14]; const float* bvm = (const float*)d_in[15];
    const float* Wvc = (const float*)d_in[16]; const float* bvc = (const float*)d_in[17];
    const float* Wom = (const float*)d_in[18]; const float* bom = (const float*)d_in[19];
    const float* Woc = (const float*)d_in[20]; const float* boc = (const float*)d_in[21];
    const float* gammas = (const float*)d_in[22];

    float* out = (float*)d_out;

    Ptr6f xs;   xs.p[0] = q_mean; xs.p[1] = q_cov; xs.p[2] = k_mean;
                xs.p[3] = k_cov;  xs.p[4] = v_mean; xs.p[5] = v_cov;
    Ptr8f ws;   ws.p[0] = Wqm; ws.p[1] = Wqc; ws.p[2] = Wkm; ws.p[3] = Wkc;
                ws.p[4] = Wvm; ws.p[5] = Wvc; ws.p[6] = Wom; ws.p[7] = Woc;
    Ptr6f bs;   bs.p[0] = bqm; bs.p[1] = bqc; bs.p[2] = bkm;
                bs.p[3] = bkc; bs.p[4] = bvm; bs.p[5] = bvc;

    u_split6  <<<dim3(MR * D / 1024, 1, 6), 256>>>(xs);
    u_splitWt8<<<dim3(D / 32, D / 32, 8), 256>>>(ws);
    u_gemm_proj<<<dim3(D / 128, MR / 128, 6), 256>>>(bs);
    u_rownorm <<<dim3(BHS / 8, 2), 256>>>();
    u_scores_wmma<<<dim3(36, BH), 256>>>();
    u_decay   <<<dim3(S / 8, BH), 256>>>(gammas);
    u_av_wmma <<<dim3(S / 128, BH), 256>>>();
    u_gemm_out<<<dim3(D / 128, MR / 128, 2), 256>>>(bom, boc, out);
}

// round 17
// speedup vs baseline: 1.1314x; 1.0990x over previous
#include <cuda_runtime.h>
#include <cuda_fp16.h>
#include <mma.h>
#include <math.h>
#include <float.h>
#include <stdint.h>

using namespace nvcuda;

constexpr int B  = 8;
constexpr int S  = 1024;
constexpr int H  = 8;
constexpr int DK = 64;
constexpr int D  = 512;
constexpr int BH  = B * H;     // 64
constexpr int BHS = BH * S;    // 65536
constexpr int MR  = B * S;     // 8192

// ---------------- device scratch ----------------
__device__ float g_att[(size_t)BH * S * S];                 // raw scores
__device__ __half g_sch[(size_t)BH * S * S];                // prob (single plane)
__device__ __half g_Qh[(size_t)BHS * 128];
__device__ __half g_Ql[(size_t)BHS * 128];
__device__ __half g_Kh[(size_t)BHS * 128];
__device__ __half g_Kl[(size_t)BHS * 128];
__device__ __half g_Vm[(size_t)BHS * DK];                   // single-plane V
__device__ __half g_Vc[(size_t)BHS * DK];
__device__ __half g_A6h[(size_t)6 * MR * D];
__device__ __half g_A6l[(size_t)6 * MR * D];                // unused (ptr slot)
__device__ __half g_W8h[8 * D * D];
__device__ __half g_W8l[8 * D * D];                         // used by out-proj only
__device__ __half g_cmh[(size_t)MR * D];
__device__ __half g_cml[(size_t)MR * D];
__device__ __half g_cch[(size_t)MR * D];
__device__ __half g_ccl[(size_t)MR * D];
// raw fp32 covariance projections (pre-sqrt) for exact tq/tk
__device__ float g_rawQc[(size_t)BHS * DK];
__device__ float g_rawKc[(size_t)BHS * DK];
__device__ float g_tq[BHS];
__device__ float g_tk[BHS];

// ---------------- cp.async helpers ----------------
#define CP16(dst, src) asm volatile( \
    "cp.async.cg.shared.global [%0], [%1], 16;" \
    :: "r"((uint32_t)__cvta_generic_to_shared(dst)), "l"(src))
#define CP_COMMIT() asm volatile("cp.async.commit_group;")
#define CP_WAIT(n)  asm volatile("cp.async.wait_group %0;" :: "n"(n))

struct Ptr6f { const float* p[6]; };
struct Ptr8f { const float* p[8]; };

// ---------------- pack 8 fp32 -> fp16 hi/lo uint4 pair --------------------
__device__ __forceinline__ void pack8h(const float* v, uint4& uh, uint4& ul)
{
    __align__(16) unsigned short hh[8];
    __align__(16) unsigned short ll[8];
#pragma unroll
    for (int c = 0; c < 8; c++) {
        const __half x = __float2half_rn(v[c]);
        hh[c] = __half_as_ushort(x);
        ll[c] = __half_as_ushort(__float2half_rn(v[c] - __half2float(x)));
    }
    uh = *(uint4*)hh;
    ul = *(uint4*)ll;
}

// ---------------- batched fp32 -> fp16 split (single plane) ----------------
__global__ void u_split6(Ptr6f xs)
{
    const size_t zo = (size_t)blockIdx.z * MR * D;
    const int i = (blockIdx.x * 256 + threadIdx.x) * 4;
    const float4 fv = *(const float4*)(xs.p[blockIdx.z] + i);
    const float v[4] = {fv.x, fv.y, fv.z, fv.w};
    __align__(8) unsigned short hh[4];
#pragma unroll
    for (int c = 0; c < 4; c++)
        hh[c] = __half_as_ushort(__float2half_rn(v[c]));
    *(uint2*)(g_A6h + zo + i) = *(uint2*)hh;
}

// ---------------- batched W[K,N] -> W^T[N,K] fp16 hi (+lo for out-proj) ----
__global__ void u_splitWt8(Ptr8f ws)
{
    __shared__ float tile[32][33];
    const size_t zo = (size_t)blockIdx.z * D * D;
    const float* W = ws.p[blockIdx.z];
    const int k0 = blockIdx.y * 32, n0 = blockIdx.x * 32;
    const int tx = threadIdx.x & 31, tw = threadIdx.x >> 5;
    for (int r = tw; r < 32; r += 8)
        tile[r][tx] = W[(size_t)(k0 + r) * D + n0 + tx];
    __syncthreads();
    for (int r = tw; r < 32; r += 8) {
        const float v = tile[tx][r];
        const size_t o = zo + (size_t)(n0 + r) * D + k0 + tx;
        g_W8h[o] = __float2half_rn(v);
    }
}

// ===================  double-buffered WMMA GEMM core  ======================
// MODE 1: aH*bH + aL*bH (2-term; skips Bl prefetch)
// MODE 2: aH*bH + aH*bL (2-term; skips Al prefetch)
// MODE 3: aH*bH         (1-term; skips Al and Bl prefetch)
constexpr int GP = 24;   // smem pitch (16 + 8 pad)

#define GEMM_PREFETCH(dstbuf, koff)                                            \
    _Pragma("unroll")                                                          \
    for (int i = 0; i < 4; i++) {                                              \
        const int c = tid + i * 256;                                           \
        const int mtx = c >> 8, rr = (c & 255) >> 1, col8 = (c & 1) * 8;       \
        const bool skip = (mtx == 1 && mode != 1) || (mtx == 3 && mode != 2);  \
        if (!skip)                                                             \
            CP16(&buf[dstbuf][mtx][rr * GP + col8],                            \
                 srcs[mtx] + (size_t)(baserow[mtx] + rr) * ldv + (koff) + col8); \
    }

#define GEMM_MAINLOOP(Ah, Al, Bh, Bl, LD, NITER, MODE)                         \
    const __half* srcs[4] = {Ah, Al, Bh, Bl};                                  \
    const int baserow[4] = {m0, m0, n0, n0};                                   \
    const int ldv = (LD);                                                      \
    const int mode = (MODE);                                                   \
    wmma::fragment<wmma::accumulator, 16, 16, 16, float> acc[4][2];            \
    _Pragma("unroll")                                                          \
    for (int mi = 0; mi < 4; mi++)                                             \
        _Pragma("unroll")                                                      \
        for (int nj = 0; nj < 2; nj++) wmma::fill_fragment(acc[mi][nj], 0.f);  \
    GEMM_PREFETCH(0, 0)                                                        \
    CP_COMMIT();                                                               \
    for (int kt = 0; kt < (NITER); kt++) {                                     \
        CP_WAIT(0);                                                            \
        __syncthreads();                                                       \
        if (kt + 1 < (NITER)) {                                                \
            const int bn = (kt + 1) & 1;                                       \
            GEMM_PREFETCH(bn, (kt + 1) * 16)                                   \
            CP_COMMIT();                                                       \
        }                                                                      \
        const __half* sAh = buf[kt & 1][0];                                    \
        const __half* sAl = buf[kt & 1][1];                                    \
        const __half* sBh = buf[kt & 1][2];                                    \
        const __half* sBl = buf[kt & 1][3];                                    \
        wmma::fragment<wmma::matrix_a, 16, 16, 16, __half, wmma::row_major> aH[4], aL[4]; \
        _Pragma("unroll")                                                      \
        for (int mi = 0; mi < 4; mi++) {                                       \
            const int row = warp_m * 64 + mi * 16;                             \
            wmma::load_matrix_sync(aH[mi], sAh + row * GP, GP);                \
            if (mode == 1) wmma::load_matrix_sync(aL[mi], sAl + row * GP, GP); \
        }                                                                      \
        _Pragma("unroll")                                                      \
        for (int nj = 0; nj < 2; nj++) {                                       \
            const int col = warp_n * 32 + nj * 16;                             \
            wmma::fragment<wmma::matrix_b, 16, 16, 16, __half, wmma::col_major> bH, bL; \
            wmma::load_matrix_sync(bH, sBh + col * GP, GP);                    \
            if (mode == 2) wmma::load_matrix_sync(bL, sBl + col * GP, GP);     \
            _Pragma("unroll")                                                  \
            for (int mi = 0; mi < 4; mi++) {                                   \
                wmma::mma_sync(acc[mi][nj], aH[mi], bH, acc[mi][nj]);          \
                if (mode == 2) wmma::mma_sync(acc[mi][nj], aH[mi], bL, acc[mi][nj]); \
                if (mode == 1) wmma::mma_sync(acc[mi][nj], aL[mi], bH, acc[mi][nj]); \
            }                                                                  \
        }                                                                      \
    }                                                                          \
    __syncthreads();

// ---------------- projection GEMM (z = 0..5), 1-term, fused epilogue -------
// z: 0 qm, 1 qc(sqrt), 2 km, 3 kc(sqrt), 4 vm, 5 vc
__global__ void __launch_bounds__(256, 2) u_gemm_proj(Ptr6f biases)
{
    __shared__ __align__(16) __half buf[2][4][128 * GP];  // 48 KB
    const int z = blockIdx.z;
    const __half* Ah = g_A6h + (size_t)z * MR * D;
    const __half* Al = g_A6l;                              // unused (mode 3)
    const __half* Bh = g_W8h + (size_t)z * D * D;
    const __half* Bl = g_W8l;                              // unused (mode 3)
    const float* bias = biases.p[z];
    const int tid = threadIdx.x, wid = tid >> 5, lane = tid & 31;
    const int m0 = blockIdx.y * 128, n0 = blockIdx.x * 128;
    const int warp_m = wid >> 2, warp_n = wid & 3;

    GEMM_MAINLOOP(Ah, Al, Bh, Bl, D, 32, 3)

    float* epi = (float*)buf + wid * 256;
#pragma unroll
    for (int mi = 0; mi < 4; mi++) {
#pragma unroll
        for (int nj = 0; nj < 2; nj++) {
            wmma::store_matrix_sync(epi, acc[mi][nj], 16, wmma::mem_row_major);
            __syncwarp();
            const int r  = lane >> 1;
            const int c0 = (lane & 1) * 8;
            const int m  = m0 + warp_m * 64 + mi * 16 + r;
            const int n  = n0 + warp_n * 32 + nj * 16 + c0;
            float v[8];
#pragma unroll
            for (int c = 0; c < 8; c++) v[c] = epi[r * 16 + c0 + c] + bias[n + c];
            const int b = m >> 10, s = m & (S - 1);
            const int h = n >> 6, d = n & 63;
            if (z < 4) {
                if (z & 1) {
                    float* raw = (z == 1) ? g_rawQc : g_rawKc;
                    const size_t ro = (((size_t)(b * H + h)) * S + s) * 64 + d;
                    *(float4*)(raw + ro)     = make_float4(v[0], v[1], v[2], v[3]);
                    *(float4*)(raw + ro + 4) = make_float4(v[4], v[5], v[6], v[7]);
#pragma unroll
                    for (int c = 0; c < 8; c++) v[c] = sqrtf(fmaxf(v[c], 1e-24f));
                }
                __half* dh = (z < 2) ? g_Qh : g_Kh;
                __half* dl = (z < 2) ? g_Ql : g_Kl;
                const size_t o = (((size_t)(b * H + h)) * S + s) * 128 + (z & 1) * 64 + d;
                uint4 uh, ul;
                pack8h(v, uh, ul);
                *(uint4*)(dh + o) = uh;
                *(uint4*)(dl + o) = ul;
            } else {
                __half* dv = (z == 4) ? g_Vm : g_Vc;
                __align__(16) unsigned short t[8];
#pragma unroll
                for (int c = 0; c < 8; c++) t[c] = __half_as_ushort(__float2half_rn(v[c]));
                const size_t o = (((size_t)(b * H + h)) * S + s) * 64 + d;
                *(uint4*)(dv + o) = *(uint4*)t;
            }
            __syncwarp();
        }
    }
}

// ---------------- output GEMM (z = 0 mean, 1 cov), 2-term ------------------
__global__ void __launch_bounds__(256, 2) u_gemm_out(const float* bias0, const float* bias1,
                                                     float* out)
{
    __shared__ __align__(16) __half buf[2][4][128 * GP];
    const int z = blockIdx.z;
    const __half* Ah = z ? g_cch : g_cmh;
    const __half* Al = z ? g_ccl : g_cml;
    const __half* Bh = g_W8h + (size_t)(6 + z) * D * D;
    const __half* Bl = g_W8l;                              // unused (mode 1)
    const float* bias = z ? bias1 : bias0;
    const int tid = threadIdx.x, wid = tid >> 5, lane = tid & 31;
    const int m0 = blockIdx.y * 128, n0 = blockIdx.x * 128;
    const int warp_m = wid >> 2, warp_n = wid & 3;

    GEMM_MAINLOOP(Ah, Al, Bh, Bl, D, 32, 1)

    float* epi = (float*)buf + wid * 256;
    float* dstm = out + (size_t)z * MR * D;
#pragma unroll
    for (int mi = 0; mi < 4; mi++) {
#pragma unroll
        for (int nj = 0; nj < 2; nj++) {
            wmma::store_matrix_sync(epi, acc[mi][nj], 16, wmma::mem_row_major);
            __syncwarp();
            const int r  = lane >> 1;
            const int c0 = (lane & 1) * 8;
            const int m  = m0 + warp_m * 64 + mi * 16 + r;
            const int n  = n0 + warp_n * 32 + nj * 16 + c0;
            float v[8];
#pragma unroll
            for (int c = 0; c < 8; c++) v[c] = epi[r * 16 + c0 + c] + bias[n + c];
            float* dst = dstm + (size_t)m * D + n;
            *(float4*)(dst)     = make_float4(v[0], v[1], v[2], v[3]);
            *(float4*)(dst + 4) = make_float4(v[4], v[5], v[6], v[7]);
            __syncwarp();
        }
    }
}

// ---------------- exact row stats: tq = sum(qm^2) + sum(raw qc) ------------
__global__ void u_rownorm()
{
    const int row  = blockIdx.x * 8 + (threadIdx.x >> 5);
    const int lane = threadIdx.x & 31;
    const __half* ph = (blockIdx.y ? g_Kh : g_Qh) + (size_t)row * 128;
    const __half* pl = (blockIdx.y ? g_Kl : g_Ql) + (size_t)row * 128;
    const float* pc = (blockIdx.y ? g_rawKc : g_rawQc) + (size_t)row * DK;
    const float a0 = __half2float(ph[lane])      + __half2float(pl[lane]);
    const float a1 = __half2float(ph[lane + 32]) + __half2float(pl[lane + 32]);
    const float c0 = pc[lane], c1 = pc[lane + 32];
    float v = a0 * a0 + a1 * a1 + c0 + c1;
#pragma unroll
    for (int o = 16; o; o >>= 1) v += __shfl_xor_sync(~0u, v, o);
    if (lane == 0) (blockIdx.y ? g_tk : g_tq)[row] = v;
}

// ---------------- WMMA scores: 128x128 causal tiles, 2-term (keep K-lo) ----
__global__ void __launch_bounds__(256, 2) u_scores_wmma()
{
    __shared__ __align__(16) __half buf[2][4][128 * GP];  // 48 KB
    const int bh = blockIdx.y;
    int tq = (int)((sqrtf(8.f * blockIdx.x + 1.f) - 1.f) * 0.5f);
    while ((tq + 1) * (tq + 2) / 2 <= (int)blockIdx.x) tq++;
    while (tq * (tq + 1) / 2 > (int)blockIdx.x) tq--;
    const int tk = blockIdx.x - tq * (tq + 1) / 2;
    const int qb = tq * 128, kb = tk * 128;

    const int tid = threadIdx.x, wid = tid >> 5, lane = tid & 31;
    const int warp_m = wid >> 2, warp_n = wid & 3;
    const int m0 = 0, n0 = 0;
    const __half* Qh = g_Qh + ((size_t)bh * S + qb) * 128;
    const __half* Ql = g_Ql + ((size_t)bh * S + qb) * 128;
    const __half* Kh = g_Kh + ((size_t)bh * S + kb) * 128;
    const __half* Kl = g_Kl + ((size_t)bh * S + kb) * 128;

    GEMM_MAINLOOP(Qh, Ql, Kh, Kl, 128, 8, 2)

    float* att = g_att + (size_t)bh * S * S;
    const float* tqv = g_tq + bh * S;
    const float* tkv = g_tk + bh * S;

    float* epi = (float*)buf + wid * 256;
#pragma unroll
    for (int mi = 0; mi < 4; mi++) {
#pragma unroll
        for (int nj = 0; nj < 2; nj++) {
            wmma::store_matrix_sync(epi, acc[mi][nj], 16, wmma::mem_row_major);
            __syncwarp();
            const int r  = lane >> 1;
            const int c0 = (lane & 1) * 8;
            const int q  = qb + warp_m * 64 + mi * 16 + r;
            const int k  = kb + warp_n * 32 + nj * 16 + c0;
            const float tq2 = tqv[q];
            float v[8];
#pragma unroll
            for (int c = 0; c < 8; c++)
                v[c] = 0.25f * epi[r * 16 + c0 + c] - 0.125f * (tq2 + tkv[k + c]);
            float* dst = att + (size_t)q * S + k;
            *(float4*)(dst)     = make_float4(v[0], v[1], v[2], v[3]);
            *(float4*)(dst + 4) = make_float4(v[4], v[5], v[6], v[7]);
            __syncwarp();
        }
    }
}

// ---------------- warp-per-row decay: softmax->cumsum->decay->softmax ------
__global__ void __launch_bounds__(256) u_decay(const float* __restrict__ gammas)
{
    const int w = threadIdx.x >> 5, lane = threadIdx.x & 31;
    const int q  = blockIdx.x * 8 + w;
    const int bh = blockIdx.y;
    const int L  = q + 1;
    const int Lr = (L + 127) & ~127;
    const float* row = g_att + ((size_t)bh * S + q) * S;

    const float g = gammas[bh & (H - 1)];
    const float gamma = -log1pf(expf(g));

    const int base = lane * 32;
    const int nv = min(32, max(0, L - base));

    float s[32];
#pragma unroll
    for (int i = 0; i < 32; i += 4) {
        if (i + 4 <= nv) {
            const float4 v = *(const float4*)(row + base + i);
            s[i] = v.x; s[i+1] = v.y; s[i+2] = v.z; s[i+3] = v.w;
        } else {
#pragma unroll
            for (int j = 0; j < 4; j++)
                s[i + j] = (i + j < nv) ? row[base + i + j] : 0.f;
        }
    }

    float m = -FLT_MAX;
#pragma unroll
    for (int i = 0; i < 32; i++) if (i < nv) m = fmaxf(m, s[i]);
#pragma unroll
    for (int o = 16; o; o >>= 1) m = fmaxf(m, __shfl_xor_sync(~0u, m, o));

    float run = 0.f;
#pragma unroll
    for (int i = 0; i < 32; i++) if (i < nv) run += expf(s[i] - m);

    float x = run;
#pragma unroll
    for (int o = 1; o < 32; o <<= 1) {
        const float y = __shfl_up_sync(~0u, x, o);
        if (lane >= o) x += y;
    }
    const float laneExcl = x - run;
    const float tot = __shfl_sync(~0u, x, 31);
    const float invT = 1.f / tot;

    float m2 = -FLT_MAX;
    float run2 = laneExcl;
#pragma unroll
    for (int i = 0; i < 32; i++) {
        if (i < nv) {
            run2 += expf(s[i] - m);
            const float cum  = run2 * invT;
            const float tail = fmaxf(1.f - cum, 0.f);
            const float pos  = (float)(q - (base + i));
            const float dist = sqrtf(tail * pos);
            float eff = expf(gamma * dist);
            eff = fminf(fmaxf(eff, 1e-5f), 1e5f);
            s[i] = s[i] * eff;
            m2 = fmaxf(m2, s[i]);
        }
    }
#pragma unroll
    for (int o = 16; o; o >>= 1) m2 = fmaxf(m2, __shfl_xor_sync(~0u, m2, o));

    float es = 0.f;
#pragma unroll
    for (int i = 0; i < 32; i++) {
        if (i < nv) {
            s[i] = expf(s[i] - m2);
            es += s[i];
        }
    }
#pragma unroll
    for (int o = 16; o; o >>= 1) es += __shfl_xor_sync(~0u, es, o);
    const float invE = 1.f / es;

    if (base < Lr) {
        const size_t pidx = ((size_t)bh * S + q) * S + base;
#pragma unroll
        for (int i = 0; i < 32; i += 8) {
            __align__(16) unsigned short t1[8];
#pragma unroll
            for (int j = 0; j < 8; j++) {
                const float pv = (q == 0 || i + j >= nv) ? 0.f : s[i + j] * invE;
                t1[j] = __half_as_ushort(__float2half_rn(pv));
            }
            *(uint4*)(g_sch + pidx + i) = *(uint4*)t1;
        }
    }
}

// ---------------- WMMA AV (1-term): mean = p@Vm, cov = p^2@Vc --------------
constexpr int AP  = 24;
constexpr int BPp = 72;

__global__ void __launch_bounds__(256, 2) u_av_wmma()
{
    __shared__ __align__(16) __half sA[2][2][128 * AP];   // [stage][{p, p^2}]
    __shared__ __align__(16) __half sB[2][2][16 * BPp];

    const int bh = blockIdx.y;
    const int qb = (7 - blockIdx.x) * 128;
    const int tid = threadIdx.x, wid = tid >> 5, lane = tid & 31;
    const int wg = wid >> 2, w4 = wid & 3;

    const size_t aoff = ((size_t)bh * S + qb) * S;
    const size_t vb   = (size_t)bh * S * DK;
    const __half* Ap0 = g_sch + aoff;
    const __half* Vp[2] = {g_Vm + vb, g_Vc + vb};

    wmma::fragment<wmma::accumulator, 16, 16, 16, float> acc[2][4];
#pragma unroll
    for (int mi = 0; mi < 2; mi++)
#pragma unroll
        for (int nj = 0; nj < 4; nj++) wmma::fill_fragment(acc[mi][nj], 0.f);

    const int NITER = (qb + 128) / 16;

#define AV_PREFETCH(bufi, kb)                                                  \
    {                                                                          \
        const int rr = tid >> 1, col8 = (tid & 1) * 8;                         \
        CP16(&sA[bufi][0][rr * AP + col8], Ap0 + (size_t)rr * S + (kb) + col8);\
        const int mtx = tid >> 7, idx = tid & 127;                             \
        const int rr2 = idx >> 3, c8 = (idx & 7) * 8;                          \
        CP16(&sB[bufi][mtx][rr2 * BPp + c8], Vp[mtx] + (size_t)((kb) + rr2) * DK + c8); \
    }

    AV_PREFETCH(0, 0)
    CP_COMMIT();

    for (int kt = 0; kt < NITER; kt++) {
        CP_WAIT(0);
        __syncthreads();
        if (kt + 1 < NITER) {
            const int bn = (kt + 1) & 1;
            AV_PREFETCH(bn, (kt + 1) * 16)
            CP_COMMIT();
        }
        const int cur = kt & 1;

        if (wg == 1) {
            const __half* src = sA[cur][0];
            __half* dst = sA[cur][1];
            const int r = w4 * 32 + lane;
#pragma unroll
            for (int c = 0; c < 16; c += 2) {
                const __half2 v = *(const __half2*)(src + r * AP + c);
                *(__half2*)(dst + r * AP + c) = __hmul2(v, v);
            }
            __syncwarp();
        }

        const __half* aPp = sA[cur][wg];
        const __half* bVp = sB[cur][wg];

        wmma::fragment<wmma::matrix_a, 16, 16, 16, __half, wmma::row_major> aP[2];
#pragma unroll
        for (int mi = 0; mi < 2; mi++) {
            const int row = w4 * 32 + mi * 16;
            wmma::load_matrix_sync(aP[mi], aPp + row * AP, AP);
        }
#pragma unroll
        for (int nj = 0; nj < 4; nj++) {
            wmma::fragment<wmma::matrix_b, 16, 16, 16, __half, wmma::row_major> bV;
            wmma::load_matrix_sync(bV, bVp + nj * 16, BPp);
#pragma unroll
            for (int mi = 0; mi < 2; mi++)
                wmma::mma_sync(acc[mi][nj], aP[mi], bV, acc[mi][nj]);
        }
    }
    __syncthreads();

    const int b = bh >> 3, h = bh & 7;
    __half* dh = wg ? g_cch : g_cmh;
    __half* dl = wg ? g_ccl : g_cml;
    float* epi = (float*)sA + wid * 256;
#pragma unroll
    for (int mi = 0; mi < 2; mi++) {
#pragma unroll
        for (int nj = 0; nj < 4; nj++) {
            wmma::store_matrix_sync(epi, acc[mi][nj], 16, wmma::mem_row_major);
            __syncwarp();
            const int r  = lane >> 1;
            const int c0 = (lane & 1) * 8;
            const int s  = qb + w4 * 32 + mi * 16 + r;
            const int d  = nj * 16 + c0;
            float v[8];
#pragma unroll
            for (int c = 0; c < 8; c++) v[c] = epi[r * 16 + c0 + c];
            uint4 uh, ul;
            pack8h(v, uh, ul);
            const size_t o = ((size_t)(b * S + s)) * D + h * DK + d;
            *(uint4*)(dh + o) = uh;
            *(uint4*)(dl + o) = ul;
            __syncwarp();
        }
    }
#undef AV_PREFETCH
}

// ---------------- host launcher --------------------------------------------
extern "C" void kernel_launch(void* const* d_in, const int* in_sizes, int n_in,
                              void* d_out, int out_size)
{
    const float* q_mean = (const float*)d_in[0];
    const float* q_cov  = (const float*)d_in[1];
    const float* k_mean = (const float*)d_in[2];
    const float* k_cov  = (const float*)d_in[3];
    const float* v_mean = (const float*)d_in[4];
    const float* v_cov  = (const float*)d_in[5];
    const float* Wqm = (const float*)d_in[6];  const float* bqm = (const float*)d_in[7];
    const float* Wqc = (const float*)d_in[8];  const float* bqc = (const float*)d_in[9];
    const float* Wkm = (const float*)d_in[10]; const float* bkm = (const float*)d_in[11];
    const float* Wkc = (const float*)d_in[12]; const float* bkc = (const float*)d_in[13];
    const float* Wvm = (const float*)d_in[14]; const float* bvm = (const float*)d_in[15];
    const float* Wvc = (const float*)d_in[16]; const float* bvc = (const float*)d_in[17];
    const float* Wom = (const float*)d_in[18]; const float* bom = (const float*)d_in[19];
    const float* Woc = (const float*)d_in[20]; const float* boc = (const float*)d_in[21];
    const float* gammas = (const float*)d_in[22];

    float* out = (float*)d_out;

    Ptr6f xs;   xs.p[0] = q_mean; xs.p[1] = q_cov; xs.p[2] = k_mean;
                xs.p[3] = k_cov;  xs.p[4] = v_mean; xs.p[5] = v_cov;
    Ptr8f ws;   ws.p[0] = Wqm; ws.p[1] = Wqc; ws.p[2] = Wkm; ws.p[3] = Wkc;
                ws.p[4] = Wvm; ws.p[5] = Wvc; ws.p[6] = Wom; ws.p[7] = Woc;
    Ptr6f bs;   bs.p[0] = bqm; bs.p[1] = bqc; bs.p[2] = bkm;
                bs.p[3] = bkc; bs.p[4] = bvm; bs.p[5] = bvc;

    u_split6  <<<dim3(MR * D / 1024, 1, 6), 256>>>(xs);
    u_splitWt8<<<dim3(D / 32, D / 32, 8), 256>>>(ws);
    u_gemm_proj<<<dim3(D / 128, MR / 128, 6), 256>>>(bs);
    u_rownorm <<<dim3(BHS / 8, 2), 256>>>();
    u_scores_wmma<<<dim3(36, BH), 256>>>();
    u_decay   <<<dim3(S / 8, BH), 256>>>(gammas);
    u_av_wmma <<<dim3(S / 128, BH), 256>>>();
    u_gemm_out<<<dim3(D / 128, MR / 128, 2), 256>>>(bom, boc, out);
}